// round 12
// baseline (speedup 1.0000x reference)
#include <cuda_runtime.h>
#include <math.h>
#include <cstdint>

// KineticsRNN R12: 2-CTA cluster hidden-split, fp32 f32x2.
// Cluster = 2 CTAs, 8 batches. CTA rank r owns hidden rows i in [64r,64r+64):
// W_hh rows {i,128+i,256+i} (96KB smem), computes h_i for all 8 batches,
// pushes its h-half to peer smem (st.shared::cluster) + mbarrier handshake.
// 256 mat threads: (il=t>>2, c=(t>>1)&1, bg=t&1) -> 3 gates x 4 batches x K-half.
// 128 aux threads: tail (head+theta+RK4+outputs) + lift for own 4 batches
// (lift replicated to peer). barA(cnt 256)=h publish; barB(cnt 384)=phase close.

#define THREADS 384
#define MATT 256
#define PITCH 136     // W_hh pitch; K-chunk1 at +68 (2-wavefront optimal)
#define CGAP 68
#define HPIT 140      // sH pitch (140%32=12: batch rows hit distinct banks)
#define LPITCH 44     // sLift pitch (44%32=12)
#define LGAP 20

#define SMEM_FLOATS (8 + 192*PITCH + 8*HPIT + 8*LPITCH + 5*PITCH + 16 + 16 + 16)
#define SMEM_BYTES  (SMEM_FLOATS*4)

typedef unsigned long long u64;

__device__ __forceinline__ u64 fma2(u64 a, u64 b, u64 c) {
    u64 d;
    asm("fma.rn.f32x2 %0, %1, %2, %3;" : "=l"(d) : "l"(a), "l"(b), "l"(c));
    return d;
}
__device__ __forceinline__ float f2sum(u64 v) {
    float2 f;
    asm("mov.b64 {%0, %1}, %2;" : "=f"(f.x), "=f"(f.y) : "l"(v));
    return f.x + f.y;
}
__device__ __forceinline__ float sigm(float x) { return __fdividef(1.f, 1.f + __expf(-x)); }
__device__ __forceinline__ float tanh_f(float x) { return 1.f - __fdividef(2.f, __expf(2.f*x) + 1.f); }
__device__ __forceinline__ uint32_t s2u(const void* p) { return (uint32_t)__cvta_generic_to_shared(p); }

#define CLSYNC() do { \
    asm volatile("barrier.cluster.arrive.aligned;" ::: "memory"); \
    asm volatile("barrier.cluster.wait.aligned;" ::: "memory"); } while (0)

#define ARRIVE_REMOTE(addr) \
    asm volatile("mbarrier.arrive.shared::cluster.b64 _, [%0];" :: "r"(addr) : "memory")

#define STCL(addr, val) \
    asm volatile("st.shared::cluster.f32 [%0], %1;" :: "r"(addr), "f"(val) : "memory")

#define MBWAIT(mb, par) do { uint32_t _d; \
    asm volatile("{\n\t.reg .pred p;\n\t" \
        "mbarrier.try_wait.parity.acquire.cluster.shared::cta.b64 p, [%1], %2;\n\t" \
        "selp.b32 %0, 1, 0, p;\n\t}" : "=r"(_d) : "r"(mb), "r"(par) : "memory"); \
    if (!_d) { asm volatile("{\n\t.reg .pred P1;\n\tWL_%=:\n\t" \
        "mbarrier.try_wait.parity.acquire.cluster.shared::cta.b64 P1, [%0], %1, 0x989680;\n\t" \
        "@P1 bra.uni WD_%=;\n\tbra.uni WL_%=;\n\tWD_%=:\n\t}" \
        :: "r"(mb), "r"(par) : "memory"); } } while (0)

__global__ __launch_bounds__(THREADS, 1) __cluster_dims__(2, 1, 1)
void krnn_cl(const float* __restrict__ y0,
             const float* __restrict__ u_seq,
             const float* __restrict__ dt_seq,
             const float* __restrict__ y_seq,
             const float* __restrict__ W_lift,
             const float* __restrict__ b_lift,
             const float* __restrict__ W_ih,
             const float* __restrict__ W_hh,
             const float* __restrict__ b_ih,
             const float* __restrict__ b_hh,
             const float* __restrict__ W_head,
             const float* __restrict__ b_head,
             const float* __restrict__ u2y,
             float* __restrict__ out,
             int B, int K)
{
    extern __shared__ float sm[];
    float* sWhh  = sm + 8;                   // 192*136 (own 192 rows, gapped)
    float* sH    = sWhh + 192*PITCH;         // 8*140 full h, all 8 batches
    float* sLift = sH + 8*HPIT;              // 8*44
    float* sWhd  = sLift + 8*LPITCH;         // 5*136
    float* sU    = sWhd + 5*PITCH;           // 4*4 (own tail batches)
    float* sYobs = sU + 16;
    float* sYtf  = sYobs + 16;

    const int t = threadIdx.x;
    uint32_t rank;
    asm("mov.u32 %0, %%cluster_ctarank;" : "=r"(rank));
    const uint32_t peer = 1u - rank;
    const int cl  = blockIdx.x >> 1;
    const int bc0 = cl * 8;                  // cluster's global batch base

    const uint32_t barA = s2u(sm);           // 8 bytes
    const uint32_t barB = barA + 8;
    uint32_t rbarA, rsH, rsLift;
    asm("mapa.shared::cluster.u32 %0, %1, %2;" : "=r"(rbarA) : "r"(barA), "r"(peer));
    asm("mapa.shared::cluster.u32 %0, %1, %2;" : "=r"(rsH) : "r"(s2u(sH)), "r"(peer));
    asm("mapa.shared::cluster.u32 %0, %1, %2;" : "=r"(rsLift) : "r"(s2u(sLift)), "r"(peer));
    const uint32_t rbarB = rbarA + 8;

    // ---- stage own 192 W_hh rows, gapped: word(row,k)=row*136+k+4*(k>=64) ----
    {
        const float4* src = (const float4*)W_hh;
        for (int idx = t; idx < 192*32; idx += THREADS) {
            int rl = idx >> 5, kb = idx & 31;
            int gate = rl >> 6, il2 = rl & 63;
            int grow = gate*128 + (int)rank*64 + il2;
            int dst = rl*PITCH + 4*kb + ((kb>>4)<<2);
            *(float4*)(sWhh + dst) = src[grow*32 + kb];
        }
    }
    for (int idx = t; idx < 5*128; idx += THREADS)
        sWhd[(idx/128)*PITCH + (idx%128)] = W_head[idx];

    // ================= mat state =================
    const int il = t >> 2, c = (t >> 1) & 1, bg = t & 1;
    const int ig = (int)rank*64 + il;
    const int gi = il + 68*(int)rank;        // word of h_i within an sH row
    u64 wr_[8], wz_[8], wn_[8];
    float cr = 0, cz = 0, bxn = 0, bhn = 0;
    if (t < MATT) {
        const ulonglong2* pr = (const ulonglong2*)(W_ih + (size_t)ig*32 + 16*c);
        const ulonglong2* pz = (const ulonglong2*)(W_ih + (size_t)(128+ig)*32 + 16*c);
        const ulonglong2* pn = (const ulonglong2*)(W_ih + (size_t)(256+ig)*32 + 16*c);
#pragma unroll
        for (int j = 0; j < 4; j++) {
            ulonglong2 vr = pr[j]; wr_[2*j] = vr.x; wr_[2*j+1] = vr.y;
            ulonglong2 vz = pz[j]; wz_[2*j] = vz.x; wz_[2*j+1] = vz.y;
            ulonglong2 vn = pn[j]; wn_[2*j] = vn.x; wn_[2*j+1] = vn.y;
        }
        cr = b_ih[ig] + b_hh[ig];
        cz = b_ih[128+ig] + b_hh[128+ig];
        bxn = b_ih[256+ig];
        bhn = b_hh[256+ig];
    }

    // ================= aux state (128 threads) =================
    const int g = t - 256;
    const int hbh = g / 5, hph = g % 5;      // head map (g<20), tail batch rank*4+hbh
    const int lr = g >> 2, lbb = g & 3;
    const int lgl = lr + ((lr >> 4) << 2);
    const int bsl = (int)rank*4;             // own tail batch slot base (local sH/sLift index)
    float bhd = 0.f;
    float wl0=0,wl1=0,wl2=0,wl3=0,wl4=0,wl5=0,blf=0;
    float yf0=0,yf1=0,yf2=0,yf3=0,yf4=0;
    float J00=0,J01=0,J02=0,J10=0,J11=0,J12=0,J20=0,J21=0,J22=0;
    float cu0=0,cu1=0,cu2=0,cdt=0;
    if (t >= MATT) {
        if (g < 20) bhd = b_head[hph];
        wl0=W_lift[lr*6+0]; wl1=W_lift[lr*6+1]; wl2=W_lift[lr*6+2];
        wl3=W_lift[lr*6+3]; wl4=W_lift[lr*6+4]; wl5=W_lift[lr*6+5];
        blf=b_lift[lr];
        if (g < 4) {
            int bgt = bc0 + bsl + g;
            yf0 = y0[bgt*3+0]; yf2 = y0[bgt*3+1]; yf4 = y0[bgt*3+2];
            J00=u2y[0];J01=u2y[1];J02=u2y[2];J10=u2y[3];J11=u2y[4];J12=u2y[5];
            J20=u2y[6];J21=u2y[7];J22=u2y[8];
            const float* up = u_seq + (size_t)bgt*K*3;
            cu0=up[0]; cu1=up[1]; cu2=up[2];
            cdt = dt_seq[(size_t)bgt*K];
            sU[g*4+0]=cu0; sU[g*4+1]=cu1; sU[g*4+2]=cu2;
            sYobs[g*4+0]=yf0; sYobs[g*4+1]=yf2; sYobs[g*4+2]=yf4;
        }
    }
    for (int idx = t; idx < 8*HPIT; idx += THREADS) sH[idx] = 0.f;
    if (t == 0) {
        asm volatile("mbarrier.init.shared.b64 [%0], %1;" :: "r"(barA), "r"(256) : "memory");
        asm volatile("mbarrier.init.shared.b64 [%0], %1;" :: "r"(barB), "r"(384) : "memory");
    }
    __syncthreads();
    CLSYNC();   // barriers + sH zeros visible cluster-wide

    // ---- prologue: lift(0) for own 4 batches, local + remote ----
    if (t >= MATT) {
        const float* ub = sU + lbb*4;
        const float* yb = sYobs + lbb*4;
        float s = blf;
        s=fmaf(wl0,ub[0],s); s=fmaf(wl1,ub[1],s); s=fmaf(wl2,ub[2],s);
        s=fmaf(wl3,yb[0],s); s=fmaf(wl4,yb[1],s); s=fmaf(wl5,yb[2],s);
        float v = s * sigm(s);
        int slot = (bsl + lbb)*LPITCH + lgl;
        sLift[slot] = v;
        STCL(rsLift + (uint32_t)slot*4, v);
    }
    __syncthreads();
    CLSYNC();   // lift(0) visible on both CTAs

    const size_t thb = (size_t)B*K*3;

    u64 aR0=0,aR1=0,aR2=0,aR3=0, aZ0=0,aZ1=0,aZ2=0,aZ3=0, aN0=0,aN1=0,aN2=0,aN3=0;
    float nu0=0,nu1=0,nu2=0,ndt=0,nt0=0,nt1=0,nt2=0;
    bool nflag = false;

    for (int k = 0; k < K; k++) {
        if (t < MATT) {
            // ---- P1: gx(k) merged into aR/aZ, aX = gxn ----
            u64 aX0=0,aX1=0,aX2=0,aX3=0;
            {
                const ulonglong2* l0 = (const ulonglong2*)(sLift + (bg*4+0)*LPITCH + LGAP*c);
                const ulonglong2* l1 = (const ulonglong2*)(sLift + (bg*4+1)*LPITCH + LGAP*c);
                const ulonglong2* l2 = (const ulonglong2*)(sLift + (bg*4+2)*LPITCH + LGAP*c);
                const ulonglong2* l3 = (const ulonglong2*)(sLift + (bg*4+3)*LPITCH + LGAP*c);
#pragma unroll
                for (int j = 0; j < 4; j++) {
                    u64 wa=wr_[2*j], wb=wr_[2*j+1], za=wz_[2*j], zb=wz_[2*j+1];
                    u64 na=wn_[2*j], nb=wn_[2*j+1];
                    ulonglong2 v0=l0[j];
                    aR0=fma2(wa,v0.x,aR0); aR0=fma2(wb,v0.y,aR0);
                    aZ0=fma2(za,v0.x,aZ0); aZ0=fma2(zb,v0.y,aZ0);
                    aX0=fma2(na,v0.x,aX0); aX0=fma2(nb,v0.y,aX0);
                    ulonglong2 v1=l1[j];
                    aR1=fma2(wa,v1.x,aR1); aR1=fma2(wb,v1.y,aR1);
                    aZ1=fma2(za,v1.x,aZ1); aZ1=fma2(zb,v1.y,aZ1);
                    aX1=fma2(na,v1.x,aX1); aX1=fma2(nb,v1.y,aX1);
                    ulonglong2 v2=l2[j];
                    aR2=fma2(wa,v2.x,aR2); aR2=fma2(wb,v2.y,aR2);
                    aZ2=fma2(za,v2.x,aZ2); aZ2=fma2(zb,v2.y,aZ2);
                    aX2=fma2(na,v2.x,aX2); aX2=fma2(nb,v2.y,aX2);
                    ulonglong2 v3=l3[j];
                    aR3=fma2(wa,v3.x,aR3); aR3=fma2(wb,v3.y,aR3);
                    aZ3=fma2(za,v3.x,aZ3); aZ3=fma2(zb,v3.y,aZ3);
                    aX3=fma2(na,v3.x,aX3); aX3=fma2(nb,v3.y,aX3);
                }
            }
            // ---- exchange across K-half partner (xor 2) ----
            float pR0=f2sum(aR0),pR1=f2sum(aR1),pR2=f2sum(aR2),pR3=f2sum(aR3);
            float pZ0=f2sum(aZ0),pZ1=f2sum(aZ1),pZ2=f2sum(aZ2),pZ3=f2sum(aZ3);
            float pN0=f2sum(aN0),pN1=f2sum(aN1),pN2=f2sum(aN2),pN3=f2sum(aN3);
            float pX0=f2sum(aX0),pX1=f2sum(aX1),pX2=f2sum(aX2),pX3=f2sum(aX3);
            float vRA=c?pR0:pR2, vRB=c?pR1:pR3, vZA=c?pZ0:pZ2, vZB=c?pZ1:pZ3;
            float vNA=c?pN0:pN2, vNB=c?pN1:pN3, vXA=c?pX0:pX2, vXB=c?pX1:pX3;
            float totRA=(c?pR2:pR0)+__shfl_xor_sync(0xffffffffu,vRA,2);
            float totRB=(c?pR3:pR1)+__shfl_xor_sync(0xffffffffu,vRB,2);
            float totZA=(c?pZ2:pZ0)+__shfl_xor_sync(0xffffffffu,vZA,2);
            float totZB=(c?pZ3:pZ1)+__shfl_xor_sync(0xffffffffu,vZB,2);
            float totNA=(c?pN2:pN0)+__shfl_xor_sync(0xffffffffu,vNA,2);
            float totNB=(c?pN3:pN1)+__shfl_xor_sync(0xffffffffu,vNB,2);
            float totXA=(c?pX2:pX0)+__shfl_xor_sync(0xffffffffu,vXA,2);
            float totXB=(c?pX3:pX1)+__shfl_xor_sync(0xffffffffu,vXB,2);
            const int bA = bg*4 + 2*c, bB = bA + 1;
            {
                float r = sigm(totRA + cr);
                float z = sigm(totZA + cz);
                float n = tanh_f(totXA + bxn + r*(totNA + bhn));
                float ho = sH[bA*HPIT + gi];
                float h = n + z*(ho - n);
                sH[bA*HPIT + gi] = h;
                STCL(rsH + (uint32_t)(bA*HPIT + gi)*4, h);
            }
            {
                float r = sigm(totRB + cr);
                float z = sigm(totZB + cz);
                float n = tanh_f(totXB + bxn + r*(totNB + bhn));
                float ho = sH[bB*HPIT + gi];
                float h = n + z*(ho - n);
                sH[bB*HPIT + gi] = h;
                STCL(rsH + (uint32_t)(bB*HPIT + gi)*4, h);
            }
            ARRIVE_REMOTE(rbarA);
            aR0=aR1=aR2=aR3=0; aZ0=aZ1=aZ2=aZ3=0; aN0=aN1=aN2=aN3=0;
        } else {
            nflag = false;
            if (g < 4 && (k+1) < K) {
                int bgt = bc0 + bsl + g;
                const float* up = u_seq + ((size_t)bgt*K + (k+1))*3;
                nu0=up[0]; nu1=up[1]; nu2=up[2];
                ndt = dt_seq[(size_t)bgt*K + (k+1)];
                nflag = ((k+1) % 50) == 0;
                if (nflag) {
                    const float* yp = y_seq + ((size_t)bgt*K + k)*3;
                    nt0=yp[0]; nt1=yp[1]; nt2=yp[2];
                }
            }
        }
        __syncthreads();
        MBWAIT(barA, k & 1);   // peer h-half(k) landed

        if (t < MATT) {
            // ---- gh(k+1) = own W_hh rows x h(k), all 8 batches' bg half ----
            const ulonglong2* wRp = (const ulonglong2*)(sWhh + il*PITCH + CGAP*c);
            const ulonglong2* wZp = (const ulonglong2*)(sWhh + (64+il)*PITCH + CGAP*c);
            const ulonglong2* wNp = (const ulonglong2*)(sWhh + (128+il)*PITCH + CGAP*c);
            const ulonglong2* x0 = (const ulonglong2*)(sH + (bg*4+0)*HPIT + CGAP*c);
            const ulonglong2* x1 = (const ulonglong2*)(sH + (bg*4+1)*HPIT + CGAP*c);
            const ulonglong2* x2 = (const ulonglong2*)(sH + (bg*4+2)*HPIT + CGAP*c);
            const ulonglong2* x3 = (const ulonglong2*)(sH + (bg*4+3)*HPIT + CGAP*c);
#pragma unroll
            for (int j = 0; j < 16; j++) {
                ulonglong2 wR=wRp[j], wZ=wZp[j], wN=wNp[j];
                ulonglong2 v0=x0[j];
                aR0=fma2(wR.x,v0.x,aR0); aR0=fma2(wR.y,v0.y,aR0);
                aZ0=fma2(wZ.x,v0.x,aZ0); aZ0=fma2(wZ.y,v0.y,aZ0);
                aN0=fma2(wN.x,v0.x,aN0); aN0=fma2(wN.y,v0.y,aN0);
                ulonglong2 v1=x1[j];
                aR1=fma2(wR.x,v1.x,aR1); aR1=fma2(wR.y,v1.y,aR1);
                aZ1=fma2(wZ.x,v1.x,aZ1); aZ1=fma2(wZ.y,v1.y,aZ1);
                aN1=fma2(wN.x,v1.x,aN1); aN1=fma2(wN.y,v1.y,aN1);
                ulonglong2 v2=x2[j];
                aR2=fma2(wR.x,v2.x,aR2); aR2=fma2(wR.y,v2.y,aR2);
                aZ2=fma2(wZ.x,v2.x,aZ2); aZ2=fma2(wZ.y,v2.y,aZ2);
                aN2=fma2(wN.x,v2.x,aN2); aN2=fma2(wN.y,v2.y,aN2);
                ulonglong2 v3=x3[j];
                aR3=fma2(wR.x,v3.x,aR3); aR3=fma2(wR.y,v3.y,aR3);
                aZ3=fma2(wZ.x,v3.x,aZ3); aZ3=fma2(wZ.y,v3.y,aZ3);
                aN3=fma2(wN.x,v3.x,aN3); aN3=fma2(wN.y,v3.y,aN3);
            }
            ARRIVE_REMOTE(rbarB);
        } else {
            // ---- tail(k): head + theta + RK4 + outputs (own 4 batches) ----
            float thv = 0.f;
            if (g < 20) {
                u64 s0 = 0, s1 = 0;
#pragma unroll
                for (int half = 0; half < 2; half++) {
                    const ulonglong2* hr = (const ulonglong2*)(sH + (bsl+hbh)*HPIT + CGAP*half);
                    const ulonglong2* wp = (const ulonglong2*)(sWhd + hph*PITCH + 64*half);
#pragma unroll
                    for (int jb = 0; jb < 16; jb++) {
                        ulonglong2 h4 = hr[jb];
                        ulonglong2 w4 = wp[jb];
                        s0 = fma2(w4.x, h4.x, s0);
                        s1 = fma2(w4.y, h4.y, s1);
                    }
                }
                float s = f2sum(s0) + f2sum(s1) + bhd;
                thv = 0.001f + 1.999f * sigm(s);
                out[thb + ((size_t)(bc0 + bsl + hbh)*K + k)*5 + hph] = thv;
            }
            if (g < 32) {
                float th0 = __shfl_sync(0xffffffffu, thv, g*5+0);
                float th1 = __shfl_sync(0xffffffffu, thv, g*5+1);
                float th2 = __shfl_sync(0xffffffffu, thv, g*5+2);
                float th3 = __shfl_sync(0xffffffffu, thv, g*5+3);
                float th4 = __shfl_sync(0xffffffffu, thv, g*5+4);
                if (g < 4) {
                    int bgt = bc0 + bsl + g;
                    yf0 += cu0*J00 + cu1*J10 + cu2*J20;
                    yf2 += cu0*J01 + cu1*J11 + cu2*J21;
                    yf4 += cu0*J02 + cu1*J12 + cu2*J22;
                    float h = cdt, hh = 0.5f*h;
#define RHS(A_,Bv,C_,D_,E_,d0,d1,d2,d3,d4) { \
    float r1=th0*(A_)*(Bv); float r2=th1*(C_); float r3=th2*(C_)*(D_); \
    float r4=th3*(E_); float r5=th4*(A_); \
    d0=-r1-r5; d1=-r1+r2; d2=r1-r2-r3; d3=-r3+r4; d4=r3-r4+r5; }
                    float a0,a1,a2,a3,a4;
                    RHS(yf0,yf1,yf2,yf3,yf4,a0,a1,a2,a3,a4);
                    float t0=yf0+hh*a0,t1=yf1+hh*a1,t2=yf2+hh*a2,t3=yf3+hh*a3,t4=yf4+hh*a4;
                    float b0,b1,b2,b3,b4v;
                    RHS(t0,t1,t2,t3,t4,b0,b1,b2,b3,b4v);
                    t0=yf0+hh*b0;t1=yf1+hh*b1;t2=yf2+hh*b2;t3=yf3+hh*b3;t4=yf4+hh*b4v;
                    float c0,c1,c2,c3,c4;
                    RHS(t0,t1,t2,t3,t4,c0,c1,c2,c3,c4);
                    t0=yf0+h*c0;t1=yf1+h*c1;t2=yf2+h*c2;t3=yf3+h*c3;t4=yf4+h*c4;
                    float d0,d1,d2,d3,d4;
                    RHS(t0,t1,t2,t3,t4,d0,d1,d2,d3,d4);
#undef RHS
                    float s6 = h*(1.f/6.f);
                    yf0=fmaxf(yf0+s6*(a0+2.f*b0+2.f*c0+d0),0.f);
                    yf1=fmaxf(yf1+s6*(a1+2.f*b1+2.f*c1+d1),0.f);
                    yf2=fmaxf(yf2+s6*(a2+2.f*b2+2.f*c2+d2),0.f);
                    yf3=fmaxf(yf3+s6*(a3+2.f*b3+2.f*c3+d3),0.f);
                    yf4=fmaxf(yf4+s6*(a4+2.f*b4v+2.f*c4+d4),0.f);
                    float* yo = out + ((size_t)bgt*K + k)*3;
                    yo[0]=yf0; yo[1]=yf2; yo[2]=yf4;
                    sYobs[g*4+0]=yf0; sYobs[g*4+1]=yf2; sYobs[g*4+2]=yf4;
                    if (k+1 < K) {
                        sU[g*4+0]=nu0; sU[g*4+1]=nu1; sU[g*4+2]=nu2;
                        if (nflag) { sYtf[g*4+0]=nt0; sYtf[g*4+1]=nt1; sYtf[g*4+2]=nt2; }
                        cu0=nu0; cu1=nu1; cu2=nu2; cdt=ndt;
                    }
                }
            }
            asm volatile("bar.sync 1, 128;" ::: "memory");
            // ---- lift(k+1), own 4 batches, local + remote ----
            {
                int kk1 = k + 1;
                bool lf = (kk1 % 50) == 0;
                const float* ub = sU + lbb*4;
                const float* yb = lf ? (sYtf + lbb*4) : (sYobs + lbb*4);
                float s = blf;
                s=fmaf(wl0,ub[0],s); s=fmaf(wl1,ub[1],s); s=fmaf(wl2,ub[2],s);
                s=fmaf(wl3,yb[0],s); s=fmaf(wl4,yb[1],s); s=fmaf(wl5,yb[2],s);
                float v = s * sigm(s);
                int slot = (bsl + lbb)*LPITCH + lgl;
                sLift[slot] = v;
                STCL(rsLift + (uint32_t)slot*4, v);
            }
            ARRIVE_REMOTE(rbarB);
        }
        __syncthreads();
        MBWAIT(barB, k & 1);   // peer done reading h(k) + peer lift(k+1) landed
    }

    CLSYNC();
}

extern "C" void kernel_launch(void* const* d_in, const int* in_sizes, int n_in,
                              void* d_out, int out_size)
{
    const float* y0     = (const float*)d_in[0];
    const float* u_seq  = (const float*)d_in[1];
    const float* dt_seq = (const float*)d_in[2];
    const float* y_seq  = (const float*)d_in[3];
    const float* W_lift = (const float*)d_in[4];
    const float* b_lift = (const float*)d_in[5];
    const float* W_ih   = (const float*)d_in[6];
    const float* W_hh   = (const float*)d_in[7];
    const float* b_ih   = (const float*)d_in[8];
    const float* b_hh   = (const float*)d_in[9];
    const float* W_head = (const float*)d_in[10];
    const float* b_head = (const float*)d_in[11];
    const float* u2y    = (const float*)d_in[12];
    float* out = (float*)d_out;

    int B = in_sizes[0] / 3;
    int K = in_sizes[2] / B;

    cudaFuncSetAttribute(krnn_cl, cudaFuncAttributeMaxDynamicSharedMemorySize, SMEM_BYTES);
    krnn_cl<<<B / 4, THREADS, SMEM_BYTES>>>(
        y0, u_seq, dt_seq, y_seq, W_lift, b_lift, W_ih, W_hh,
        b_ih, b_hh, W_head, b_head, u2y, out, B, K);
}